// round 14
// baseline (speedup 1.0000x reference)
#include <cuda_runtime.h>
#include <cuda_fp16.h>
#include <cstdint>

#define N_NEURON 4096
#define N_BATCH  32
#define N_STEPS  300
#define NCTA     128

// ---------------- device scratch (allocation-free rule: __device__ globals) ----
__device__ __align__(256) __half g_W16[(size_t)N_NEURON * N_NEURON];
__device__ __align__(256) __half g_r16[2][N_BATCH * N_NEURON];
__device__ __align__(256) unsigned g_cnt2[128];   // [0]=half0, [64]=half1 (256B apart)
__device__ __align__(256) unsigned g_gen2[128];

// ---------------- W fp32 -> fp16 fragment pack (once per replay) --------------
__global__ void convert_w(const float* __restrict__ W) {
    int idx = blockIdx.x * blockDim.x + threadIdx.x;
    if (idx >= 128 * 256 * 32) return;
    int lane = idx & 31;
    int kb   = (idx >> 5) & 255;
    int jt   = idx >> 13;
    int k0   = kb * 16 + (lane & 3) * 2;
    int g    = lane >> 2;
    __half h[16];
    #pragma unroll
    for (int nb = 0; nb < 4; ++nb) {
        int j = jt * 32 + nb * 8 + g;
        h[nb * 4 + 0] = __float2half(W[(size_t)(k0    ) * N_NEURON + j]);
        h[nb * 4 + 1] = __float2half(W[(size_t)(k0 + 1) * N_NEURON + j]);
        h[nb * 4 + 2] = __float2half(W[(size_t)(k0 + 8) * N_NEURON + j]);
        h[nb * 4 + 3] = __float2half(W[(size_t)(k0 + 9) * N_NEURON + j]);
    }
    uint4* dst = (uint4*)(g_W16 + (size_t)idx * 16);
    dst[0] = ((const uint4*)h)[0];
    dst[1] = ((const uint4*)h)[1];
}

// ---------------- smem layout ---------------------------------------------------
#define WC_KB        208                      // kb entries cached in smem (of 256)
#define PLANE_BYTES  (WC_KB * 512)            // 106496 per plane
#define RED_OFF      (2 * PLANE_BYTES)        // 212992
#define RED_BYTES    (8 * 16 * 32 * 4)        // 16384 (half-batch reduction)
#define SMEM_TOTAL   (RED_OFF + RED_BYTES)    // 229376 = 224 KB

#define SM_KB_W      26                       // smem kbs per warp (208/8)
#define TL_KB_W      6                        // L2-tail kbs per warp (48/8)

__device__ __forceinline__ unsigned ld_acq(unsigned* p) {
    unsigned v;
    asm volatile("ld.acquire.gpu.global.u32 %0, [%1];" : "=r"(v) : "l"(p) : "memory");
    return v;
}
// split barrier, fence-free (acq_rel arrival chain + release/acquire gen word)
__device__ __forceinline__ void bar_arrive(int tid, unsigned* cnt, unsigned* gen, unsigned target) {
    __syncthreads();
    if (tid == 0) {
        unsigned arr;
        asm volatile("atom.add.acq_rel.gpu.global.u32 %0, [%1], 1;"
                     : "=r"(arr) : "l"(cnt) : "memory");
        if (arr == NCTA - 1) {
            asm volatile("st.global.u32 [%0], %1;" :: "l"(cnt), "r"(0u) : "memory");
            asm volatile("st.release.gpu.global.u32 [%0], %1;"
                         :: "l"(gen), "r"(target) : "memory");
        }
    }
}
__device__ __forceinline__ void bar_wait(int tid, unsigned* gen, unsigned target) {
    if (tid == 0) {
        while ((int)(ld_acq(gen) - target) < 0) {}
    }
    __syncthreads();
}

__device__ __forceinline__ void lds128(uint4& d, uint32_t addr) {
    asm volatile("ld.shared.v4.u32 {%0,%1,%2,%3}, [%4];"
        : "=r"(d.x), "=r"(d.y), "=r"(d.z), "=r"(d.w) : "r"(addr));
}
__device__ __forceinline__ void stcg32(void* p, uint32_t v) {
    asm volatile("st.global.cg.u32 [%0], %1;" :: "l"(p), "r"(v) : "memory");
}
__device__ __forceinline__ uint32_t h2u(float a, float b) {
    __half2 h = __floats2half2_rn(a, b);
    return *(uint32_t*)&h;
}
__device__ __forceinline__ void mma_16816(float c[4], const uint4& a, uint32_t b0, uint32_t b1) {
    asm volatile("mma.sync.aligned.m16n8k16.row.col.f32.f16.f16.f32 "
        "{%0,%1,%2,%3}, {%4,%5,%6,%7}, {%8,%9}, {%0,%1,%2,%3};\n"
        : "+f"(c[0]), "+f"(c[1]), "+f"(c[2]), "+f"(c[3])
        : "r"(a.x), "r"(a.y), "r"(a.z), "r"(a.w), "r"(b0), "r"(b1));
}
// kb index used by warp at iteration i of 32 (13 smem + 3 tail per 16)
__device__ __forceinline__ int kb_of(int warp, int i) {
    int grp = i >> 4, r = i & 15;
    return (r < 13) ? (warp * SM_KB_W + grp * 13 + r)
                    : (WC_KB + warp * TL_KB_W + grp * 3 + (r - 13));
}

// ---------------- persistent fused simulation kernel ---------------------------
__global__ void __launch_bounds__(256, 1) persist_kernel(
    const float* __restrict__ ff, const float* __restrict__ rec0,
    float* __restrict__ out)
{
    extern __shared__ __align__(16) char sm[];
    float* red = (float*)(sm + RED_OFF);

    const int tid  = threadIdx.x;
    const int warp = tid >> 5;
    const int lane = tid & 31;
    const int jt   = blockIdx.x;
    const int j0   = jt * 32;

    uint32_t smbase;
    asm("{ .reg .u64 t0; cvta.to.shared.u64 t0, %1; cvt.u32.u64 %0, t0; }"
        : "=r"(smbase) : "l"(sm));

    const uint4* __restrict__ gB = (const uint4*)g_W16 + (size_t)jt * 256 * 64;

    // epilogue ownership: thread -> (local row bbl, 2 consecutive j) per half
    const int bbl = tid >> 4;          // 0..15
    const int jl  = (tid & 15) * 2;    // 0..30 even
    const int j   = j0 + jl;

    unsigned* cnt0 = &g_cnt2[0];
    unsigned* gen0 = &g_gen2[0];
    unsigned* cnt1 = &g_cnt2[64];
    unsigned* gen1 = &g_gen2[64];

    const unsigned base0 = ld_acq(gen0);   // replay-safe bases
    const unsigned base1 = ld_acq(gen1);

    // ---- prologue: cache 208 kb-entries of W stripe into two smem planes ------
    {
        const char* src = (const char*)gB;
        for (int s = tid; s < WC_KB * 32; s += 256) {
            uint32_t d0 = smbase + s * 16;
            uint32_t d1 = smbase + PLANE_BYTES + s * 16;
            const char* g0 = src + (size_t)s * 32;
            asm volatile("cp.async.cg.shared.global [%0], [%1], 16;" :: "r"(d0), "l"(g0));
            asm volatile("cp.async.cg.shared.global [%0], [%1], 16;" :: "r"(d1), "l"(g0 + 16));
        }
        asm volatile("cp.async.commit_group;");
        asm volatile("cp.async.wait_group 0;");
    }

    // ---- state init in registers (both halves); publish A generation 0 --------
    float rc[2][2], rt[2][2], av[2][2];
    #pragma unroll
    for (int h = 0; h < 2; ++h) {
        const int bb = h * 16 + bbl;
        const size_t idx = (size_t)bb * N_NEURON + j;
        float2 r0 = *(const float2*)&rec0[idx];
        float2 f0 = __ldcg((const float2*)&ff[((size_t)bb * N_STEPS) * N_NEURON + j]);
        rc[h][0] = r0.x; rc[h][1] = r0.y;
        rt[h][0] = fmaxf(f0.x + r0.x, 0.f);
        rt[h][1] = fmaxf(f0.y + r0.y, 0.f);
        av[h][0] = av[h][1] = 0.f;
        int kb = j >> 4, kk = j & 15;
        int reg   = ((bbl >> 3) & 1) | ((kk >> 3) << 1);
        int lane0 = ((bbl & 7) << 2) | ((kk & 7) >> 1);
        __half2* basep = (__half2*)g_r16[0];
        stcg32(&basep[((size_t)(kb * 2 + h) * 32 + lane0) * 4 + reg], h2u(rt[h][0], rt[h][1]));
    }
    bar_arrive(tid, cnt0, gen0, base0 + 1);
    bar_arrive(tid, cnt1, gen1, base1 + 1);

    const float E_SYN  = 0.95122942450071403f;
    const float DT_SYN = 0.05f;
    const float E_TAU  = 0.90483741803595957f;
    const float DT_TAU = 0.1f;

    for (int t = 0; t < N_STEPS; ++t) {
        const int cur = t & 1, nxt = cur ^ 1;
        const uint4* __restrict__ gA = (const uint4*)g_r16[cur];

        #pragma unroll
        for (int h = 0; h < 2; ++h) {
            const int bb = h * 16 + bbl;
            unsigned* cnt = h ? cnt1 : cnt0;
            unsigned* gen = h ? gen1 : gen0;
            const unsigned base = h ? base1 : base0;

            const float2 ffv =
                __ldcg((const float2*)&ff[((size_t)bb * N_STEPS + t) * N_NEURON + j]);

            float c[4][4];
            #pragma unroll
            for (int nb = 0; nb < 4; ++nb)
                #pragma unroll
                for (int x = 0; x < 4; ++x) c[nb][x] = 0.f;

            // ---- un-gated W prefetches (overlap wait/skew) ----
            uint4 Bg0[3], Bg1[3], Bs0[2], Bs1[2];
            #pragma unroll
            for (int p = 0; p < 3; ++p) {
                int kg = WC_KB + warp * TL_KB_W + p;
                Bg0[p] = __ldg(&gB[((size_t)kg * 32 + lane) * 2 + 0]);
                Bg1[p] = __ldg(&gB[((size_t)kg * 32 + lane) * 2 + 1]);
            }
            {
                uint32_t off = smbase + (uint32_t)((warp * SM_KB_W) * 512 + lane * 16);
                lds128(Bs0[0], off);
                lds128(Bs1[0], off + PLANE_BYTES);
            }

            // ---- wait: all CTAs published half h of generation t ----
            bar_wait(tid, gen, base + 1 + (unsigned)t);

            // ---- A prefetch ring (gated, L2-coherent, this half only) ----
            uint4 Ar[3];
            #pragma unroll
            for (int p = 0; p < 3; ++p) {
                int ka = kb_of(warp, p);
                Ar[p] = __ldcg(&gA[((size_t)ka * 2 + h) * 32 + lane]);
            }

            #pragma unroll
            for (int i = 0; i < 32; ++i) {
                const int grp = i >> 4, r = i & 15;
                uint4 A0 = Ar[i % 3];
                uint4 B0, B1;
                if (r < 13) {
                    const int s = grp * 13 + r;
                    B0 = Bs0[s & 1]; B1 = Bs1[s & 1];
                    if (s + 1 < SM_KB_W) {
                        uint32_t off = smbase +
                            (uint32_t)((warp * SM_KB_W + s + 1) * 512 + lane * 16);
                        lds128(Bs0[(s + 1) & 1], off);
                        lds128(Bs1[(s + 1) & 1], off + PLANE_BYTES);
                    }
                } else {
                    const int g = grp * 3 + (r - 13);
                    B0 = Bg0[g % 3]; B1 = Bg1[g % 3];
                    if (g + 3 < TL_KB_W) {
                        int kg = WC_KB + warp * TL_KB_W + g + 3;
                        Bg0[g % 3] = __ldg(&gB[((size_t)kg * 32 + lane) * 2 + 0]);
                        Bg1[g % 3] = __ldg(&gB[((size_t)kg * 32 + lane) * 2 + 1]);
                    }
                }

                mma_16816(c[0], A0, B0.x, B0.y);
                mma_16816(c[1], A0, B0.z, B0.w);
                mma_16816(c[2], A0, B1.x, B1.y);
                mma_16816(c[3], A0, B1.z, B1.w);

                if (i + 3 < 32) {
                    int nk = kb_of(warp, i + 3);
                    Ar[i % 3] = __ldcg(&gA[((size_t)nk * 2 + h) * 32 + lane]);
                }
            }

            // ---- cross-warp k-reduction (16x32 per warp buffer) ----
            float* myred = red + warp * (16 * 32);
            #pragma unroll
            for (int nb = 0; nb < 4; ++nb)
                #pragma unroll
                for (int x = 0; x < 4; ++x) {
                    int m = (lane >> 2) + ((x >= 2) ? 8 : 0);
                    int n = nb * 8 + (lane & 3) * 2 + (x & 1);
                    myred[m * 32 + n] = c[nb][x];
                }
            __syncthreads();

            float hs[2] = {0.f, 0.f};
            #pragma unroll
            for (int ww = 0; ww < 8; ++ww) {
                float2 p = *(const float2*)&red[ww * (16 * 32) + bbl * 32 + jl];
                hs[0] += p.x; hs[1] += p.y;
            }

            const float fv[2] = {ffv.x, ffv.y};
            #pragma unroll
            for (int x = 0; x < 2; ++x) {
                rc[h][x] = rc[h][x] * E_SYN + hs[x] * DT_SYN;
                float nl = fmaxf(fv[x] + rc[h][x], 0.0f);
                rt[h][x] = rt[h][x] * E_TAU + nl * DT_TAU;
            }

            // publish next-step A fragments for this half, then arrive
            {
                int kb = j >> 4, kk = j & 15;
                int reg   = ((bbl >> 3) & 1) | ((kk >> 3) << 1);
                int lane0 = ((bbl & 7) << 2) | ((kk & 7) >> 1);
                __half2* basep = (__half2*)g_r16[nxt];
                stcg32(&basep[((size_t)(kb * 2 + h) * 32 + lane0) * 4 + reg],
                       h2u(rt[h][0], rt[h][1]));
            }
            bar_arrive(tid, cnt, gen, base + 2 + (unsigned)t);

            // window accumulation + output (after arrive — off the critical path)
            if (t >= 90) {
                av[h][0] += rt[h][0]; av[h][1] += rt[h][1];
                if (t >= 100 && ((t - 100) % 10) == 0) {
                    const int w = (t - 100) / 10;
                    float* o = &out[((size_t)bb * 20 + w) * N_NEURON + j];
                    asm volatile("st.global.cg.v2.f32 [%0], {%1,%2};"
                        :: "l"(o), "f"(av[h][0] * 0.1f), "f"(av[h][1] * 0.1f) : "memory");
                    av[h][0] = av[h][1] = 0.f;
                }
            }
        }
    }
}

// ---------------- launch ------------------------------------------------------
extern "C" void kernel_launch(void* const* d_in, const int* in_sizes, int n_in,
                              void* d_out, int out_size) {
    const float* W    = (const float*)d_in[0];   // Wab_T [4096,4096] f32
    const float* ff   = (const float*)d_in[1];   // ff_input [32,300,4096] f32
    const float* rec0 = (const float*)d_in[2];   // rec0 [32,4096] f32
    float* out = (float*)d_out;                  // [32,20,4096] f32

    cudaFuncSetAttribute(persist_kernel, cudaFuncAttributeMaxDynamicSharedMemorySize, SMEM_TOTAL);

    convert_w<<<(128 * 256 * 32 + 255) / 256, 256>>>(W);
    persist_kernel<<<NCTA, 256, SMEM_TOTAL>>>(ff, rec0, out);
}

// round 15
// speedup vs baseline: 1.4894x; 1.4894x over previous
#include <cuda_runtime.h>
#include <cuda_fp16.h>
#include <cstdint>

#define N_NEURON 4096
#define N_BATCH  32
#define N_STEPS  300
#define NCTA     128

// ---------------- device scratch (allocation-free rule: __device__ globals) ----
__device__ __align__(256) __half g_W16[(size_t)N_NEURON * N_NEURON];
__device__ __align__(256) __half g_r16[2][N_BATCH * N_NEURON];
__device__ __align__(256) unsigned g_cnt;     // monotonic arrival counter

// ---------------- reset (runs first each launch/replay) ------------------------
__global__ void reset_kernel() { g_cnt = 0u; }

// ---------------- W fp32 -> fp16 fragment pack (once per replay) --------------
__global__ void convert_w(const float* __restrict__ W) {
    int idx = blockIdx.x * blockDim.x + threadIdx.x;
    if (idx >= 128 * 256 * 32) return;
    int lane = idx & 31;
    int kb   = (idx >> 5) & 255;
    int jt   = idx >> 13;
    int k0   = kb * 16 + (lane & 3) * 2;
    int g    = lane >> 2;
    __half h[16];
    #pragma unroll
    for (int nb = 0; nb < 4; ++nb) {
        int j = jt * 32 + nb * 8 + g;
        h[nb * 4 + 0] = __float2half(W[(size_t)(k0    ) * N_NEURON + j]);
        h[nb * 4 + 1] = __float2half(W[(size_t)(k0 + 1) * N_NEURON + j]);
        h[nb * 4 + 2] = __float2half(W[(size_t)(k0 + 8) * N_NEURON + j]);
        h[nb * 4 + 3] = __float2half(W[(size_t)(k0 + 9) * N_NEURON + j]);
    }
    uint4* dst = (uint4*)(g_W16 + (size_t)idx * 16);
    dst[0] = ((const uint4*)h)[0];
    dst[1] = ((const uint4*)h)[1];
}

// ---------------- smem layout ---------------------------------------------------
#define WC_KB        192
#define PLANE_BYTES  (WC_KB * 512)            // 98304 per plane
#define RED_OFF      (2 * PLANE_BYTES)        // 196608
#define RED_BYTES    (8 * 32 * 32 * 4)        // 32768
#define SMEM_TOTAL   (RED_OFF + RED_BYTES)    // 229376 = 224 KB

__device__ __forceinline__ unsigned ld_acq(unsigned* p) {
    unsigned v;
    asm volatile("ld.acquire.gpu.global.u32 %0, [%1];" : "=r"(v) : "l"(p) : "memory");
    return v;
}

// fire-and-forget barrier: release-red arrival (no return), all CTAs poll count.
// target for step s = NCTA * (s+1); counter is monotonic within a launch.
__device__ __forceinline__ void grid_barrier(int tid, unsigned target) {
    __syncthreads();                    // all warps' publishes issued
    if (tid == 0) {
        asm volatile("red.release.gpu.global.add.u32 [%0], %1;"
                     :: "l"(&g_cnt), "r"(1u) : "memory");
        while ((int)(ld_acq(&g_cnt) - target) < 0) {}
    }
    __syncthreads();
}

__device__ __forceinline__ void lds128(uint4& d, uint32_t addr) {
    asm volatile("ld.shared.v4.u32 {%0,%1,%2,%3}, [%4];"
        : "=r"(d.x), "=r"(d.y), "=r"(d.z), "=r"(d.w) : "r"(addr));
}
__device__ __forceinline__ void stcg32(void* p, uint32_t v) {
    asm volatile("st.global.cg.u32 [%0], %1;" :: "l"(p), "r"(v) : "memory");
}
__device__ __forceinline__ uint32_t h2u(float a, float b) {
    __half2 h = __floats2half2_rn(a, b);
    return *(uint32_t*)&h;
}
__device__ __forceinline__ void mma_16816(float c[4], const uint4& a, uint32_t b0, uint32_t b1) {
    asm volatile("mma.sync.aligned.m16n8k16.row.col.f32.f16.f16.f32 "
        "{%0,%1,%2,%3}, {%4,%5,%6,%7}, {%8,%9}, {%0,%1,%2,%3};\n"
        : "+f"(c[0]), "+f"(c[1]), "+f"(c[2]), "+f"(c[3])
        : "r"(a.x), "r"(a.y), "r"(a.z), "r"(a.w), "r"(b0), "r"(b1));
}
// kb index used by warp at mainloop iteration i (3 smem + 1 tail per 4 iters)
__device__ __forceinline__ int kb_of(int warp, int i) {
    int g = i >> 2, r = i & 3;
    return (r < 3) ? (warp * 24 + g * 3 + r) : (WC_KB + warp * 8 + g);
}

// ---------------- persistent fused simulation kernel ---------------------------
__global__ void __launch_bounds__(256, 1) persist_kernel(
    const float* __restrict__ ff, const float* __restrict__ rec0,
    float* __restrict__ out)
{
    extern __shared__ __align__(16) char sm[];
    float* red = (float*)(sm + RED_OFF);

    const int tid  = threadIdx.x;
    const int warp = tid >> 5;
    const int lane = tid & 31;
    const int jt   = blockIdx.x;
    const int j0   = jt * 32;

    uint32_t smbase;
    asm("{ .reg .u64 t0; cvta.to.shared.u64 t0, %1; cvt.u32.u64 %0, t0; }"
        : "=r"(smbase) : "l"(sm));

    const uint4* __restrict__ gB = (const uint4*)g_W16 + (size_t)jt * 256 * 64;

    const int bb = tid >> 3;
    const int jl = (tid & 7) * 4;
    const int j  = j0 + jl;

    // ---- prologue: cache first 192 kb-entries of W stripe into two smem planes
    {
        const char* src = (const char*)gB;
        for (int s = tid; s < WC_KB * 32; s += 256) {
            uint32_t d0 = smbase + s * 16;
            uint32_t d1 = smbase + PLANE_BYTES + s * 16;
            const char* g0 = src + (size_t)s * 32;
            asm volatile("cp.async.cg.shared.global [%0], [%1], 16;" :: "r"(d0), "l"(g0));
            asm volatile("cp.async.cg.shared.global [%0], [%1], 16;" :: "r"(d1), "l"(g0 + 16));
        }
        asm volatile("cp.async.commit_group;");
        asm volatile("cp.async.wait_group 0;");
    }

    // ---- state init in registers; publish A generation 0 ----
    float rc[4], rt[4], av[4];
    {
        const size_t idx = (size_t)bb * N_NEURON + j;
        float4 r0 = *(const float4*)&rec0[idx];
        float4 f0 = __ldg((const float4*)&ff[((size_t)bb * N_STEPS) * N_NEURON + j]);
        rc[0] = r0.x; rc[1] = r0.y; rc[2] = r0.z; rc[3] = r0.w;
        rt[0] = fmaxf(f0.x + r0.x, 0.f); rt[1] = fmaxf(f0.y + r0.y, 0.f);
        rt[2] = fmaxf(f0.z + r0.z, 0.f); rt[3] = fmaxf(f0.w + r0.w, 0.f);
        av[0] = av[1] = av[2] = av[3] = 0.f;
        int kb = j >> 4, kk = j & 15;
        int rb2 = bb >> 4, g = bb & 7;
        int reg   = ((bb >> 3) & 1) | ((kk >> 3) << 1);
        int lane0 = (g << 2) | ((kk & 7) >> 1);
        __half2* basep = (__half2*)g_r16[0];
        stcg32(&basep[((size_t)(kb * 2 + rb2) * 32 + lane0    ) * 4 + reg], h2u(rt[0], rt[1]));
        stcg32(&basep[((size_t)(kb * 2 + rb2) * 32 + lane0 + 1) * 4 + reg], h2u(rt[2], rt[3]));
    }
    grid_barrier(tid, NCTA);           // arrival 1: init publishes visible

    const float E_SYN  = 0.95122942450071403f;
    const float DT_SYN = 0.05f;
    const float E_TAU  = 0.90483741803595957f;
    const float DT_TAU = 0.1f;

    for (int t = 0; t < N_STEPS; ++t) {
        const int cur = t & 1, nxt = cur ^ 1;
        const uint4* __restrict__ gA = (const uint4*)g_r16[cur];

        const float4 ffv = __ldg((const float4*)&ff[((size_t)bb * N_STEPS + t) * N_NEURON + j]);

        float c[2][4][4];
        #pragma unroll
        for (int rb = 0; rb < 2; ++rb)
            #pragma unroll
            for (int nb = 0; nb < 4; ++nb)
                #pragma unroll
                for (int i = 0; i < 4; ++i) c[rb][nb][i] = 0.f;

        // ---- prefetch rings: A (3), B tail (3), B smem dbl-buf ----
        uint4 Ar0[3], Ar1[3], Bg0[3], Bg1[3], Bs0[2], Bs1[2];
        #pragma unroll
        for (int p = 0; p < 3; ++p) {
            int ka = kb_of(warp, p);
            Ar0[p] = __ldcg(&gA[((size_t)ka * 2 + 0) * 32 + lane]);
            Ar1[p] = __ldcg(&gA[((size_t)ka * 2 + 1) * 32 + lane]);
            int kg = WC_KB + warp * 8 + p;
            Bg0[p] = __ldg(&gB[((size_t)kg * 32 + lane) * 2 + 0]);
            Bg1[p] = __ldg(&gB[((size_t)kg * 32 + lane) * 2 + 1]);
        }
        {
            uint32_t off = smbase + (uint32_t)((warp * 24) * 512 + lane * 16);
            lds128(Bs0[0], off);
            lds128(Bs1[0], off + PLANE_BYTES);
        }

        #pragma unroll
        for (int i = 0; i < 32; ++i) {
            const int g = i >> 2, r = i & 3;
            uint4 A0 = Ar0[i % 3], A1 = Ar1[i % 3];
            uint4 B0, B1;
            if (r < 3) {
                const int s = g * 3 + r;
                B0 = Bs0[s & 1]; B1 = Bs1[s & 1];
                if (s + 1 < 24) {
                    uint32_t off = smbase + (uint32_t)((warp * 24 + s + 1) * 512 + lane * 16);
                    lds128(Bs0[(s + 1) & 1], off);
                    lds128(Bs1[(s + 1) & 1], off + PLANE_BYTES);
                }
            } else {
                B0 = Bg0[g % 3]; B1 = Bg1[g % 3];
                if (g + 3 < 8) {
                    int kg = WC_KB + warp * 8 + g + 3;
                    Bg0[g % 3] = __ldg(&gB[((size_t)kg * 32 + lane) * 2 + 0]);
                    Bg1[g % 3] = __ldg(&gB[((size_t)kg * 32 + lane) * 2 + 1]);
                }
            }

            mma_16816(c[0][0], A0, B0.x, B0.y);
            mma_16816(c[0][1], A0, B0.z, B0.w);
            mma_16816(c[0][2], A0, B1.x, B1.y);
            mma_16816(c[0][3], A0, B1.z, B1.w);
            mma_16816(c[1][0], A1, B0.x, B0.y);
            mma_16816(c[1][1], A1, B0.z, B0.w);
            mma_16816(c[1][2], A1, B1.x, B1.y);
            mma_16816(c[1][3], A1, B1.z, B1.w);

            if (i + 3 < 32) {
                int nk = kb_of(warp, i + 3);
                Ar0[i % 3] = __ldcg(&gA[((size_t)nk * 2 + 0) * 32 + lane]);
                Ar1[i % 3] = __ldcg(&gA[((size_t)nk * 2 + 1) * 32 + lane]);
            }
        }

        // ---- cross-warp k-reduction through smem (single phase, as in R6) ----
        float* myred = red + warp * (32 * 32);
        #pragma unroll
        for (int rb = 0; rb < 2; ++rb)
            #pragma unroll
            for (int nb = 0; nb < 4; ++nb)
                #pragma unroll
                for (int i = 0; i < 4; ++i) {
                    int m = rb * 16 + (lane >> 2) + ((i >= 2) ? 8 : 0);
                    int n = nb * 8 + (lane & 3) * 2 + (i & 1);
                    myred[m * 32 + n] = c[rb][nb][i];
                }
        __syncthreads();

        float h[4] = {0.f, 0.f, 0.f, 0.f};
        #pragma unroll
        for (int ww = 0; ww < 8; ++ww) {
            float4 p = *(const float4*)&red[ww * (32 * 32) + bb * 32 + jl];
            h[0] += p.x; h[1] += p.y; h[2] += p.z; h[3] += p.w;
        }

        const float fv[4] = {ffv.x, ffv.y, ffv.z, ffv.w};
        #pragma unroll
        for (int x = 0; x < 4; ++x) {
            rc[x] = rc[x] * E_SYN + h[x] * DT_SYN;
            float nl = fmaxf(fv[x] + rc[x], 0.0f);
            rt[x] = rt[x] * E_TAU + nl * DT_TAU;
        }

        {
            int kb = j >> 4, kk = j & 15;
            int rb2 = bb >> 4, g = bb & 7;
            int reg   = ((bb >> 3) & 1) | ((kk >> 3) << 1);
            int lane0 = (g << 2) | ((kk & 7) >> 1);
            __half2* basep = (__half2*)g_r16[nxt];
            stcg32(&basep[((size_t)(kb * 2 + rb2) * 32 + lane0    ) * 4 + reg], h2u(rt[0], rt[1]));
            stcg32(&basep[((size_t)(kb * 2 + rb2) * 32 + lane0 + 1) * 4 + reg], h2u(rt[2], rt[3]));
        }

        if (t >= 90) {
            av[0] += rt[0]; av[1] += rt[1]; av[2] += rt[2]; av[3] += rt[3];
            if (t >= 100 && ((t - 100) % 10) == 0) {
                const int w = (t - 100) / 10;
                *(float4*)&out[((size_t)bb * 20 + w) * N_NEURON + j] =
                    make_float4(av[0] * 0.1f, av[1] * 0.1f, av[2] * 0.1f, av[3] * 0.1f);
                av[0] = av[1] = av[2] = av[3] = 0.f;
            }
        }

        if (t < N_STEPS - 1) grid_barrier(tid, (unsigned)(NCTA * (t + 2)));
    }
}

// ---------------- launch ------------------------------------------------------
extern "C" void kernel_launch(void* const* d_in, const int* in_sizes, int n_in,
                              void* d_out, int out_size) {
    const float* W    = (const float*)d_in[0];   // Wab_T [4096,4096] f32
    const float* ff   = (const float*)d_in[1];   // ff_input [32,300,4096] f32
    const float* rec0 = (const float*)d_in[2];   // rec0 [32,4096] f32
    float* out = (float*)d_out;                  // [32,20,4096] f32

    cudaFuncSetAttribute(persist_kernel, cudaFuncAttributeMaxDynamicSharedMemorySize, SMEM_TOTAL);

    reset_kernel<<<1, 1>>>();
    convert_w<<<(128 * 256 * 32 + 255) / 256, 256>>>(W);
    persist_kernel<<<NCTA, 256, SMEM_TOTAL>>>(ff, rec0, out);
}

// round 16
// speedup vs baseline: 1.5480x; 1.0393x over previous
#include <cuda_runtime.h>
#include <cuda_fp16.h>
#include <cstdint>

#define N_NEURON 4096
#define N_BATCH  32
#define N_STEPS  300
#define NCTA     128

// ---------------- device scratch (allocation-free rule: __device__ globals) ----
__device__ __align__(256) __half g_W16[(size_t)N_NEURON * N_NEURON];
__device__ __align__(256) __half g_r16[2][N_BATCH * N_NEURON];
__device__ __align__(256) unsigned g_cnt;     // monotonic arrival counter

// ---------------- reset (runs first each launch/replay) ------------------------
__global__ void reset_kernel() { g_cnt = 0u; }

// ---------------- W fp32 -> fp16 fragment pack (once per replay) --------------
__global__ void convert_w(const float* __restrict__ W) {
    int idx = blockIdx.x * blockDim.x + threadIdx.x;
    if (idx >= 128 * 256 * 32) return;
    int lane = idx & 31;
    int kb   = (idx >> 5) & 255;
    int jt   = idx >> 13;
    int k0   = kb * 16 + (lane & 3) * 2;
    int g    = lane >> 2;
    __half h[16];
    #pragma unroll
    for (int nb = 0; nb < 4; ++nb) {
        int j = jt * 32 + nb * 8 + g;
        h[nb * 4 + 0] = __float2half(W[(size_t)(k0    ) * N_NEURON + j]);
        h[nb * 4 + 1] = __float2half(W[(size_t)(k0 + 1) * N_NEURON + j]);
        h[nb * 4 + 2] = __float2half(W[(size_t)(k0 + 8) * N_NEURON + j]);
        h[nb * 4 + 3] = __float2half(W[(size_t)(k0 + 9) * N_NEURON + j]);
    }
    uint4* dst = (uint4*)(g_W16 + (size_t)idx * 16);
    dst[0] = ((const uint4*)h)[0];
    dst[1] = ((const uint4*)h)[1];
}

// ---------------- smem layout ---------------------------------------------------
#define WC_KB        192
#define PLANE_BYTES  (WC_KB * 512)            // 98304 per plane
#define RED_OFF      (2 * PLANE_BYTES)        // 196608
#define RED_BYTES    (8 * 32 * 32 * 4)        // 32768
#define SMEM_TOTAL   (RED_OFF + RED_BYTES)    // 229376 = 224 KB

__device__ __forceinline__ unsigned ld_acq(unsigned* p) {
    unsigned v;
    asm volatile("ld.acquire.gpu.global.u32 %0, [%1];" : "=r"(v) : "l"(p) : "memory");
    return v;
}

// fire-and-forget barrier: release-red arrival (no return), all CTAs poll count.
__device__ __forceinline__ void grid_barrier(int tid, unsigned target) {
    __syncthreads();                    // all warps' publishes issued (and STS drained)
    if (tid == 0) {
        asm volatile("red.release.gpu.global.add.u32 [%0], %1;"
                     :: "l"(&g_cnt), "r"(1u) : "memory");
        while ((int)(ld_acq(&g_cnt) - target) < 0) {}
    }
    __syncthreads();
}

__device__ __forceinline__ void lds128(uint4& d, uint32_t addr) {
    asm volatile("ld.shared.v4.u32 {%0,%1,%2,%3}, [%4];"
        : "=r"(d.x), "=r"(d.y), "=r"(d.z), "=r"(d.w) : "r"(addr));
}
__device__ __forceinline__ void stcg32(void* p, uint32_t v) {
    asm volatile("st.global.cg.u32 [%0], %1;" :: "l"(p), "r"(v) : "memory");
}
__device__ __forceinline__ uint32_t h2u(float a, float b) {
    __half2 h = __floats2half2_rn(a, b);
    return *(uint32_t*)&h;
}
__device__ __forceinline__ void mma_16816(float c[4], const uint4& a, uint32_t b0, uint32_t b1) {
    asm volatile("mma.sync.aligned.m16n8k16.row.col.f32.f16.f16.f32 "
        "{%0,%1,%2,%3}, {%4,%5,%6,%7}, {%8,%9}, {%0,%1,%2,%3};\n"
        : "+f"(c[0]), "+f"(c[1]), "+f"(c[2]), "+f"(c[3])
        : "r"(a.x), "r"(a.y), "r"(a.z), "r"(a.w), "r"(b0), "r"(b1));
}
// kb index used by warp at mainloop iteration i (3 smem + 1 tail per 4 iters)
__device__ __forceinline__ int kb_of(int warp, int i) {
    int g = i >> 2, r = i & 3;
    return (r < 3) ? (warp * 24 + g * 3 + r) : (WC_KB + warp * 8 + g);
}

// ---------------- persistent fused simulation kernel ---------------------------
__global__ void __launch_bounds__(256, 1) persist_kernel(
    const float* __restrict__ ff, const float* __restrict__ rec0,
    float* __restrict__ out)
{
    extern __shared__ __align__(16) char sm[];
    float* red = (float*)(sm + RED_OFF);

    const int tid  = threadIdx.x;
    const int warp = tid >> 5;
    const int lane = tid & 31;
    const int jt   = blockIdx.x;
    const int j0   = jt * 32;

    uint32_t smbase;
    asm("{ .reg .u64 t0; cvta.to.shared.u64 t0, %1; cvt.u32.u64 %0, t0; }"
        : "=r"(smbase) : "l"(sm));

    const uint4* __restrict__ gB = (const uint4*)g_W16 + (size_t)jt * 256 * 64;

    const int bb = tid >> 3;
    const int jl = (tid & 7) * 4;
    const int j  = j0 + jl;

    // ---- prologue: cache first 192 kb-entries of W stripe into two smem planes
    {
        const char* src = (const char*)gB;
        for (int s = tid; s < WC_KB * 32; s += 256) {
            uint32_t d0 = smbase + s * 16;
            uint32_t d1 = smbase + PLANE_BYTES + s * 16;
            const char* g0 = src + (size_t)s * 32;
            asm volatile("cp.async.cg.shared.global [%0], [%1], 16;" :: "r"(d0), "l"(g0));
            asm volatile("cp.async.cg.shared.global [%0], [%1], 16;" :: "r"(d1), "l"(g0 + 16));
        }
        asm volatile("cp.async.commit_group;");
        asm volatile("cp.async.wait_group 0;");
    }

    // ---- state init in registers; publish A generation 0 ----
    float rc[4], rt[4], av[4];
    {
        const size_t idx = (size_t)bb * N_NEURON + j;
        float4 r0 = *(const float4*)&rec0[idx];
        float4 f0 = __ldg((const float4*)&ff[((size_t)bb * N_STEPS) * N_NEURON + j]);
        rc[0] = r0.x; rc[1] = r0.y; rc[2] = r0.z; rc[3] = r0.w;
        rt[0] = fmaxf(f0.x + r0.x, 0.f); rt[1] = fmaxf(f0.y + r0.y, 0.f);
        rt[2] = fmaxf(f0.z + r0.z, 0.f); rt[3] = fmaxf(f0.w + r0.w, 0.f);
        av[0] = av[1] = av[2] = av[3] = 0.f;
        int kb = j >> 4, kk = j & 15;
        int rb2 = bb >> 4, g = bb & 7;
        int reg   = ((bb >> 3) & 1) | ((kk >> 3) << 1);
        int lane0 = (g << 2) | ((kk & 7) >> 1);
        __half2* basep = (__half2*)g_r16[0];
        stcg32(&basep[((size_t)(kb * 2 + rb2) * 32 + lane0    ) * 4 + reg], h2u(rt[0], rt[1]));
        stcg32(&basep[((size_t)(kb * 2 + rb2) * 32 + lane0 + 1) * 4 + reg], h2u(rt[2], rt[3]));
    }
    grid_barrier(tid, NCTA);           // arrival 1: init publishes visible

    const float E_SYN  = 0.95122942450071403f;
    const float DT_SYN = 0.05f;
    const float E_TAU  = 0.90483741803595957f;
    const float DT_TAU = 0.1f;

    for (int t = 0; t < N_STEPS; ++t) {
        const int cur = t & 1, nxt = cur ^ 1;
        const uint4* __restrict__ gA = (const uint4*)g_r16[cur];

        const float4 ffv = __ldg((const float4*)&ff[((size_t)bb * N_STEPS + t) * N_NEURON + j]);

        float c[2][4][4];
        #pragma unroll
        for (int rb = 0; rb < 2; ++rb)
            #pragma unroll
            for (int nb = 0; nb < 4; ++nb)
                #pragma unroll
                for (int i = 0; i < 4; ++i) c[rb][nb][i] = 0.f;

        // ---- prefetch rings: A (3), B tail (3), B smem dbl-buf ----
        uint4 Ar0[3], Ar1[3], Bg0[3], Bg1[3], Bs0[2], Bs1[2];
        #pragma unroll
        for (int p = 0; p < 3; ++p) {
            int ka = kb_of(warp, p);
            Ar0[p] = __ldcg(&gA[((size_t)ka * 2 + 0) * 32 + lane]);
            Ar1[p] = __ldcg(&gA[((size_t)ka * 2 + 1) * 32 + lane]);
            int kg = WC_KB + warp * 8 + p;
            Bg0[p] = __ldg(&gB[((size_t)kg * 32 + lane) * 2 + 0]);
            Bg1[p] = __ldg(&gB[((size_t)kg * 32 + lane) * 2 + 1]);
        }
        {
            uint32_t off = smbase + (uint32_t)((warp * 24) * 512 + lane * 16);
            lds128(Bs0[0], off);
            lds128(Bs1[0], off + PLANE_BYTES);
        }

        #pragma unroll
        for (int i = 0; i < 32; ++i) {
            const int g = i >> 2, r = i & 3;
            uint4 A0 = Ar0[i % 3], A1 = Ar1[i % 3];
            uint4 B0, B1;
            if (r < 3) {
                const int s = g * 3 + r;
                B0 = Bs0[s & 1]; B1 = Bs1[s & 1];
                if (s + 1 < 24) {
                    uint32_t off = smbase + (uint32_t)((warp * 24 + s + 1) * 512 + lane * 16);
                    lds128(Bs0[(s + 1) & 1], off);
                    lds128(Bs1[(s + 1) & 1], off + PLANE_BYTES);
                }
            } else {
                B0 = Bg0[g % 3]; B1 = Bg1[g % 3];
                if (g + 3 < 8) {
                    int kg = WC_KB + warp * 8 + g + 3;
                    Bg0[g % 3] = __ldg(&gB[((size_t)kg * 32 + lane) * 2 + 0]);
                    Bg1[g % 3] = __ldg(&gB[((size_t)kg * 32 + lane) * 2 + 1]);
                }
            }

            mma_16816(c[0][0], A0, B0.x, B0.y);
            mma_16816(c[0][1], A0, B0.z, B0.w);
            mma_16816(c[0][2], A0, B1.x, B1.y);
            mma_16816(c[0][3], A0, B1.z, B1.w);
            mma_16816(c[1][0], A1, B0.x, B0.y);
            mma_16816(c[1][1], A1, B0.z, B0.w);
            mma_16816(c[1][2], A1, B1.x, B1.y);
            mma_16816(c[1][3], A1, B1.z, B1.w);

            if (i + 3 < 32) {
                int nk = kb_of(warp, i + 3);
                Ar0[i % 3] = __ldcg(&gA[((size_t)nk * 2 + 0) * 32 + lane]);
                Ar1[i % 3] = __ldcg(&gA[((size_t)nk * 2 + 1) * 32 + lane]);
            }
        }

        // ---- cross-warp k-reduction: swizzled float2 stores (degree<=2 banks) --
        float* myred = red + warp * (32 * 32);
        #pragma unroll
        for (int rb = 0; rb < 2; ++rb)
            #pragma unroll
            for (int nb = 0; nb < 4; ++nb)
                #pragma unroll
                for (int half = 0; half < 2; ++half) {
                    int m = rb * 16 + (lane >> 2) + half * 8;
                    int n = nb * 8 + (lane & 3) * 2;
                    int word = m * 32 + ((n + 4 * m) & 31);
                    *(float2*)&myred[word] =
                        make_float2(c[rb][nb][half * 2], c[rb][nb][half * 2 + 1]);
                }
        __syncthreads();

        float h[4] = {0.f, 0.f, 0.f, 0.f};
        {
            const int word = bb * 32 + ((jl + 4 * bb) & 31);
            #pragma unroll
            for (int ww = 0; ww < 8; ++ww) {
                float4 p = *(const float4*)&red[ww * (32 * 32) + word];
                h[0] += p.x; h[1] += p.y; h[2] += p.z; h[3] += p.w;
            }
        }

        const float fv[4] = {ffv.x, ffv.y, ffv.z, ffv.w};
        #pragma unroll
        for (int x = 0; x < 4; ++x) {
            rc[x] = rc[x] * E_SYN + h[x] * DT_SYN;
            float nl = fmaxf(fv[x] + rc[x], 0.0f);
            rt[x] = rt[x] * E_TAU + nl * DT_TAU;
        }

        {
            int kb = j >> 4, kk = j & 15;
            int rb2 = bb >> 4, g = bb & 7;
            int reg   = ((bb >> 3) & 1) | ((kk >> 3) << 1);
            int lane0 = (g << 2) | ((kk & 7) >> 1);
            __half2* basep = (__half2*)g_r16[nxt];
            stcg32(&basep[((size_t)(kb * 2 + rb2) * 32 + lane0    ) * 4 + reg], h2u(rt[0], rt[1]));
            stcg32(&basep[((size_t)(kb * 2 + rb2) * 32 + lane0 + 1) * 4 + reg], h2u(rt[2], rt[3]));
        }

        if (t >= 90) {
            av[0] += rt[0]; av[1] += rt[1]; av[2] += rt[2]; av[3] += rt[3];
            if (t >= 100 && ((t - 100) % 10) == 0) {
                const int w = (t - 100) / 10;
                *(float4*)&out[((size_t)bb * 20 + w) * N_NEURON + j] =
                    make_float4(av[0] * 0.1f, av[1] * 0.1f, av[2] * 0.1f, av[3] * 0.1f);
                av[0] = av[1] = av[2] = av[3] = 0.f;
            }
        }

        if (t < N_STEPS - 1) grid_barrier(tid, (unsigned)(NCTA * (t + 2)));
    }
}

// ---------------- launch ------------------------------------------------------
extern "C" void kernel_launch(void* const* d_in, const int* in_sizes, int n_in,
                              void* d_out, int out_size) {
    const float* W    = (const float*)d_in[0];   // Wab_T [4096,4096] f32
    const float* ff   = (const float*)d_in[1];   // ff_input [32,300,4096] f32
    const float* rec0 = (const float*)d_in[2];   // rec0 [32,4096] f32
    float* out = (float*)d_out;                  // [32,20,4096] f32

    cudaFuncSetAttribute(persist_kernel, cudaFuncAttributeMaxDynamicSharedMemorySize, SMEM_TOTAL);

    reset_kernel<<<1, 1>>>();
    convert_w<<<(128 * 256 * 32 + 255) / 256, 256>>>(W);
    persist_kernel<<<NCTA, 256, SMEM_TOTAL>>>(ff, rec0, out);
}